// round 2
// baseline (speedup 1.0000x reference)
#include <cuda_runtime.h>
#include <mma.h>
#include <math.h>

using namespace nvcuda;

#define N_NODES_C 20000
#define N_EDGES_C 320000
#define NH 128
#define DIN 262
#define KPAD 272          // DIN padded to multiple of 16
#define NLAYERS 3
#define BN_EPS 1e-5f
#define N_TILES (N_EDGES_C / 64)   // 5000
#define GRID_P 148                 // persistent grid (1 CTA/SM)

// ---------------- scratch ----------------
__device__ float g_x[N_NODES_C * NH];            // working node features (10.24 MB)
__device__ float g_h1[(size_t)N_EDGES_C * NH];   // hpre (163.84 MB)
__device__ float g_norm[N_EDGES_C];
__device__ float g_dot[N_EDGES_C];
__device__ float g_stats[2 * NH];                // col sums / sumsq
__device__ float g_bnA[NH];                      // BN scale
__device__ float g_bnB[NH];                      // BN shift
__device__ float g_agg[N_NODES_C * NH];          // segment-sum accumulator

__device__ __forceinline__ float psi_f(float z) {
    return copysignf(log1pf(fabsf(z)), z);
}
__device__ __forceinline__ float sigmoid_f(float z) {
    return 1.0f / (1.0f + expf(-z));
}
__device__ __forceinline__ float tf32r(float x) {
    return wmma::__float_to_tf32(x);
}

// ---------------- per-edge Minkowski norms/dots --------------------------------------
__global__ void k_prep(const int* __restrict__ ei) {
    int e = blockIdx.x * 8 + (threadIdx.x >> 5);
    if (e >= N_EDGES_C) return;
    int lane = threadIdx.x & 31;
    int r = ei[e];
    int c = ei[N_EDGES_C + e];
    const float* xi = g_x + (size_t)r * NH;
    const float* xj = g_x + (size_t)c * NH;
    float dd = 0.f, ij = 0.f;
#pragma unroll
    for (int t = 0; t < 4; t++) {
        int k = lane + 32 * t;
        float a = xi[k], b = xj[k];
        float d = a - b;
        float sgn = (k == 0) ? 1.f : -1.f;
        dd = fmaf(sgn * d, d, dd);
        ij = fmaf(sgn * a, b, ij);
    }
#pragma unroll
    for (int o = 16; o; o >>= 1) {
        dd += __shfl_xor_sync(0xffffffffu, dd, o);
        ij += __shfl_xor_sync(0xffffffffu, ij, o);
    }
    if (lane == 0) {
        g_norm[e] = psi_f(dd);
        g_dot[e]  = psi_f(ij);
    }
}

// ---------------- GEMM1 (persistent, W1 smem-resident, fused BN stats) ---------------
// block = 256 threads (8 warps, 2x4), tile = 64 edges x 128 cols, warp tile 32x32.
// smem: W1s [272][132] + As [64][276] (also reused as 64x132 output staging) + idx.
__global__ void __launch_bounds__(256, 1)
k_gemm1(const int* __restrict__ ei, const float* __restrict__ ea,
        const float* __restrict__ W1) {
    extern __shared__ float sm[];
    float* W1s = sm;                       // 272*132
    float* As  = sm + KPAD * 132;          // 64*276 (staging reuse: 64*132)
    int*   srow = (int*)(As + 64 * 276);   // 64
    int*   scol = srow + 64;               // 64

    int tid = threadIdx.x;
    int warp = tid >> 5;
    int wy = warp >> 2, wx = warp & 3;     // 2 x 4 warp grid

    // load W1 once (pre-rounded tf32), zero the K padding
    for (int idx = tid; idx < DIN * NH; idx += 256) {
        int k = idx >> 7, c = idx & 127;
        W1s[k * 132 + c] = tf32r(W1[idx]);
    }
    for (int idx = tid; idx < (KPAD - DIN) * NH; idx += 256) {
        int k = DIN + (idx >> 7), c = idx & 127;
        W1s[k * 132 + c] = 0.f;
    }

    float st_s = 0.f, st_q = 0.f;          // per-thread BN stats (fixed column)
    int myc = tid & 127;
    int myh = tid >> 7;                    // row half (0/1)

    for (int tile = blockIdx.x; tile < N_TILES; tile += GRID_P) {
        int e0 = tile * 64;
        __syncthreads();                   // protect As/srow reuse
        if (tid < 64) srow[tid] = ei[e0 + tid];
        else if (tid < 128) scol[tid - 64] = ei[N_EDGES_C + e0 + tid - 64];
        __syncthreads();

        // gather A tile: 64 edges x 68 float4 groups, pre-rounded
        for (int idx = tid; idx < 64 * 68; idx += 256) {
            int e = idx / 68, g = idx - e * 68;
            int kg = g * 4;
            float4 v;
            if (kg < 128)       v = *(const float4*)&g_x[(size_t)srow[e] * NH + kg];
            else if (kg < 256)  v = *(const float4*)&g_x[(size_t)scol[e] * NH + (kg - 128)];
            else if (kg == 256) v = *(const float4*)&ea[(size_t)(e0 + e) * 4];
            else if (kg == 260) v = make_float4(g_norm[e0 + e], g_dot[e0 + e], 0.f, 0.f);
            else                v = make_float4(0.f, 0.f, 0.f, 0.f);
            float* dst = &As[e * 276 + kg];
            dst[0] = tf32r(v.x); dst[1] = tf32r(v.y);
            dst[2] = tf32r(v.z); dst[3] = tf32r(v.w);
        }
        __syncthreads();

        wmma::fragment<wmma::accumulator, 16, 16, 8, float> acc[2][2];
#pragma unroll
        for (int i = 0; i < 2; i++)
#pragma unroll
            for (int j = 0; j < 2; j++) wmma::fill_fragment(acc[i][j], 0.f);

        for (int kk = 0; kk < KPAD; kk += 8) {
            wmma::fragment<wmma::matrix_a, 16, 16, 8, wmma::precision::tf32, wmma::row_major> a0, a1;
            wmma::fragment<wmma::matrix_b, 16, 16, 8, wmma::precision::tf32, wmma::row_major> b0, b1;
            wmma::load_matrix_sync(a0, &As[(wy * 32) * 276 + kk], 276);
            wmma::load_matrix_sync(a1, &As[(wy * 32 + 16) * 276 + kk], 276);
            wmma::load_matrix_sync(b0, &W1s[kk * 132 + wx * 32], 132);
            wmma::load_matrix_sync(b1, &W1s[kk * 132 + wx * 32 + 16], 132);
            wmma::mma_sync(acc[0][0], a0, b0, acc[0][0]);
            wmma::mma_sync(acc[0][1], a0, b1, acc[0][1]);
            wmma::mma_sync(acc[1][0], a1, b0, acc[1][0]);
            wmma::mma_sync(acc[1][1], a1, b1, acc[1][1]);
        }
        __syncthreads();                   // all warps done reading As

        // stage output to smem (reuse As as 64x132)
#pragma unroll
        for (int i = 0; i < 2; i++)
#pragma unroll
            for (int j = 0; j < 2; j++)
                wmma::store_matrix_sync(&As[(wy * 32 + i * 16) * 132 + wx * 32 + j * 16],
                                        acc[i][j], 132, wmma::mem_row_major);
        __syncthreads();

        // write h1 (coalesced) + accumulate BN stats in registers
#pragma unroll
        for (int r = 0; r < 32; r++) {
            int e = myh * 32 + r;
            float v = As[e * 132 + myc];
            g_h1[(size_t)(e0 + e) * NH + myc] = v;
            st_s += v;
            st_q = fmaf(v, v, st_q);
        }
    }
    atomicAdd(&g_stats[myc], st_s);
    atomicAdd(&g_stats[NH + myc], st_q);
}

// ---------------- BN finalize (also resets stats for next layer) ---------------------
__global__ void k_bnfin(const float* __restrict__ gamma, const float* __restrict__ beta) {
    int c = threadIdx.x;
    float inv = 1.f / (float)N_EDGES_C;
    float mean = g_stats[c] * inv;
    float var = g_stats[NH + c] * inv - mean * mean;
    float sc = gamma[c] * rsqrtf(var + BN_EPS);
    g_bnA[c] = sc;
    g_bnB[c] = beta[c] - mean * sc;
    g_stats[c] = 0.f;
    g_stats[NH + c] = 0.f;
}

// ---------------- fused (persistent, W2+Wa smem-resident) ----------------------------
// BN+ReLU -> GEMM W2 -> bias+ReLU+gate -> GEMM Wa -> bias+ReLU+Wb dot -> clip+scatter.
__global__ void __launch_bounds__(256, 1)
k_fused(const int* __restrict__ ei,
        const float* __restrict__ W2, const float* __restrict__ b2,
        const float* __restrict__ Wa, const float* __restrict__ ba,
        const float* __restrict__ Wb,
        const float* __restrict__ Wm, const float* __restrict__ bm) {
    extern __shared__ float sm[];
    float* W2s = sm;                         // 128*132
    float* Was = W2s + NH * 132;             // 128*132
    float* S0  = Was + NH * 132;             // 64*132
    float* S1  = S0 + 64 * 132;              // 64*132
    float* p_bnA = S1 + 64 * 132;            // 128
    float* p_bnB = p_bnA + NH;               // 128
    float* p_b2  = p_bnB + NH;               // 128
    float* p_ba  = p_b2 + NH;                // 128
    float* p_Wm  = p_ba + NH;                // 128
    float* p_Wb  = p_Wm + NH;                // 128
    float* s_sh  = p_Wb + NH;                // 64
    int*   srow  = (int*)(s_sh + 64);        // 64
    int*   scol  = srow + 64;                // 64

    int tid = threadIdx.x;
    int warp = tid >> 5, lane = tid & 31;
    int wy = warp >> 2, wx = warp & 3;
    float bmv = bm[0];

    for (int idx = tid; idx < NH * NH; idx += 256) {
        int k = idx >> 7, c = idx & 127;
        W2s[k * 132 + c] = tf32r(W2[idx]);
        Was[k * 132 + c] = tf32r(Wa[idx]);
    }
    if (tid < NH) {
        p_bnA[tid] = g_bnA[tid];
        p_bnB[tid] = g_bnB[tid];
        p_b2[tid]  = b2[tid];
        p_ba[tid]  = ba[tid];
        p_Wm[tid]  = Wm[tid];
        p_Wb[tid]  = Wb[tid];
    }

    for (int tile = blockIdx.x; tile < N_TILES; tile += GRID_P) {
        int e0 = tile * 64;
        __syncthreads();                     // protect smem reuse across tiles
        if (tid < 64) srow[tid] = ei[e0 + tid];
        else if (tid < 128) scol[tid - 64] = ei[N_EDGES_C + e0 + tid - 64];

        // BN + ReLU -> S0 (pre-rounded)
        for (int idx = tid; idx < 64 * 32; idx += 256) {
            int e = idx >> 5, g = idx & 31;
            int kg = g * 4;
            float4 v = *(const float4*)&g_h1[(size_t)(e0 + e) * NH + kg];
            float* dst = &S0[e * 132 + kg];
            dst[0] = tf32r(fmaxf(fmaf(v.x, p_bnA[kg + 0], p_bnB[kg + 0]), 0.f));
            dst[1] = tf32r(fmaxf(fmaf(v.y, p_bnA[kg + 1], p_bnB[kg + 1]), 0.f));
            dst[2] = tf32r(fmaxf(fmaf(v.z, p_bnA[kg + 2], p_bnB[kg + 2]), 0.f));
            dst[3] = tf32r(fmaxf(fmaf(v.w, p_bnA[kg + 3], p_bnB[kg + 3]), 0.f));
        }
        __syncthreads();

        // GEMM: S1 = S0 @ W2
        {
            wmma::fragment<wmma::accumulator, 16, 16, 8, float> acc[2][2];
#pragma unroll
            for (int i = 0; i < 2; i++)
#pragma unroll
                for (int j = 0; j < 2; j++) wmma::fill_fragment(acc[i][j], 0.f);
            for (int kk = 0; kk < NH; kk += 8) {
                wmma::fragment<wmma::matrix_a, 16, 16, 8, wmma::precision::tf32, wmma::row_major> a0, a1;
                wmma::fragment<wmma::matrix_b, 16, 16, 8, wmma::precision::tf32, wmma::row_major> b0, b1;
                wmma::load_matrix_sync(a0, &S0[(wy * 32) * 132 + kk], 132);
                wmma::load_matrix_sync(a1, &S0[(wy * 32 + 16) * 132 + kk], 132);
                wmma::load_matrix_sync(b0, &W2s[kk * 132 + wx * 32], 132);
                wmma::load_matrix_sync(b1, &W2s[kk * 132 + wx * 32 + 16], 132);
                wmma::mma_sync(acc[0][0], a0, b0, acc[0][0]);
                wmma::mma_sync(acc[0][1], a0, b1, acc[0][1]);
                wmma::mma_sync(acc[1][0], a1, b0, acc[1][0]);
                wmma::mma_sync(acc[1][1], a1, b1, acc[1][1]);
            }
#pragma unroll
            for (int i = 0; i < 2; i++)
#pragma unroll
                for (int j = 0; j < 2; j++)
                    wmma::store_matrix_sync(&S1[(wy * 32 + i * 16) * 132 + wx * 32 + j * 16],
                                            acc[i][j], 132, wmma::mem_row_major);
        }
        __syncthreads();

        // bias + ReLU + sigmoid gate (warp handles 8 edges), write gated+rounded back
#pragma unroll
        for (int t = 0; t < 8; t++) {
            int e = warp * 8 + t;
            float v[4];
            float p = 0.f;
#pragma unroll
            for (int u = 0; u < 4; u++) {
                int c = lane + 32 * u;
                v[u] = fmaxf(S1[e * 132 + c] + p_b2[c], 0.f);
                p = fmaf(v[u], p_Wm[c], p);
            }
#pragma unroll
            for (int o = 16; o; o >>= 1) p += __shfl_xor_sync(0xffffffffu, p, o);
            float wg = sigmoid_f(p + bmv);
#pragma unroll
            for (int u = 0; u < 4; u++) {
                int c = lane + 32 * u;
                S1[e * 132 + c] = tf32r(v[u] * wg);
            }
        }
        __syncthreads();

        // GEMM: S0 = S1 @ Wa
        {
            wmma::fragment<wmma::accumulator, 16, 16, 8, float> acc[2][2];
#pragma unroll
            for (int i = 0; i < 2; i++)
#pragma unroll
                for (int j = 0; j < 2; j++) wmma::fill_fragment(acc[i][j], 0.f);
            for (int kk = 0; kk < NH; kk += 8) {
                wmma::fragment<wmma::matrix_a, 16, 16, 8, wmma::precision::tf32, wmma::row_major> a0, a1;
                wmma::fragment<wmma::matrix_b, 16, 16, 8, wmma::precision::tf32, wmma::row_major> b0, b1;
                wmma::load_matrix_sync(a0, &S1[(wy * 32) * 132 + kk], 132);
                wmma::load_matrix_sync(a1, &S1[(wy * 32 + 16) * 132 + kk], 132);
                wmma::load_matrix_sync(b0, &Was[kk * 132 + wx * 32], 132);
                wmma::load_matrix_sync(b1, &Was[kk * 132 + wx * 32 + 16], 132);
                wmma::mma_sync(acc[0][0], a0, b0, acc[0][0]);
                wmma::mma_sync(acc[0][1], a0, b1, acc[0][1]);
                wmma::mma_sync(acc[1][0], a1, b0, acc[1][0]);
                wmma::mma_sync(acc[1][1], a1, b1, acc[1][1]);
            }
#pragma unroll
            for (int i = 0; i < 2; i++)
#pragma unroll
                for (int j = 0; j < 2; j++)
                    wmma::store_matrix_sync(&S0[(wy * 32 + i * 16) * 132 + wx * 32 + j * 16],
                                            acc[i][j], 132, wmma::mem_row_major);
        }
        __syncthreads();

        // s = (ReLU(S0 + ba)) . Wb per edge
#pragma unroll
        for (int t = 0; t < 8; t++) {
            int e = warp * 8 + t;
            float p = 0.f;
#pragma unroll
            for (int u = 0; u < 4; u++) {
                int c = lane + 32 * u;
                p = fmaf(fmaxf(S0[e * 132 + c] + p_ba[c], 0.f), p_Wb[c], p);
            }
#pragma unroll
            for (int o = 16; o; o >>= 1) p += __shfl_xor_sync(0xffffffffu, p, o);
            if (lane == 0) s_sh[e] = p;
        }
        __syncthreads();

        // trans = clip(x_diff * s); segment-sum scatter
        for (int idx = tid; idx < 64 * NH; idx += 256) {
            int el = idx >> 7, k = idx & 127;
            int r = srow[el], c = scol[el];
            float d = g_x[(size_t)r * NH + k] - g_x[(size_t)c * NH + k];
            float v = d * s_sh[el];
            v = fminf(fmaxf(v, -100.f), 100.f);
            atomicAdd(&g_agg[(size_t)r * NH + k], v);
        }
    }
}

// ---------------- x += agg; agg = 0 (ready for next layer / next replay) -------------
__global__ void k_apply() {
    int i = blockIdx.x * 256 + threadIdx.x;
    if (i < N_NODES_C * NH) {
        g_x[i] += g_agg[i];
        g_agg[i] = 0.f;
    }
}

// ---------------- head: sigmoid(x @ We + be) ------------------------------------------
__global__ void k_head(const float* __restrict__ We, const float* __restrict__ be,
                       float* __restrict__ out) {
    int n = blockIdx.x * 8 + (threadIdx.x >> 5);
    if (n >= N_NODES_C) return;
    int lane = threadIdx.x & 31;
    const float* xr = g_x + (size_t)n * NH;
    float p0 = 0.f, p1 = 0.f;
#pragma unroll
    for (int u = 0; u < 4; u++) {
        int k = lane + 32 * u;
        float v = xr[k];
        p0 = fmaf(v, We[k * 2 + 0], p0);
        p1 = fmaf(v, We[k * 2 + 1], p1);
    }
#pragma unroll
    for (int o = 16; o; o >>= 1) {
        p0 += __shfl_xor_sync(0xffffffffu, p0, o);
        p1 += __shfl_xor_sync(0xffffffffu, p1, o);
    }
    if (lane == 0) {
        out[(size_t)n * 2 + 0] = sigmoid_f(p0 + be[0]);
        out[(size_t)n * 2 + 1] = sigmoid_f(p1 + be[1]);
    }
}

// ---------------- launch --------------------------------------------------------------
extern "C" void kernel_launch(void* const* d_in, const int* in_sizes, int n_in,
                              void* d_out, int out_size) {
    (void)in_sizes; (void)n_in; (void)out_size;
    const float* x     = (const float*)d_in[0];
    const int*   ei    = (const int*)d_in[1];
    const float* ea    = (const float*)d_in[2];
    const float* W1    = (const float*)d_in[3];
    const float* gamma = (const float*)d_in[4];
    const float* beta  = (const float*)d_in[5];
    const float* W2    = (const float*)d_in[6];
    const float* b2    = (const float*)d_in[7];
    const float* Wa    = (const float*)d_in[8];
    const float* ba    = (const float*)d_in[9];
    const float* Wb    = (const float*)d_in[10];
    const float* Wm    = (const float*)d_in[11];
    const float* bm    = (const float*)d_in[12];
    const float* We    = (const float*)d_in[13];
    const float* be    = (const float*)d_in[14];
    float* out = (float*)d_out;

    const int smem_gemm1 = (KPAD * 132 + 64 * 276) * 4 + 2 * 64 * 4;
    const int smem_fused = (2 * NH * 132 + 2 * 64 * 132 + 6 * NH + 64) * 4 + 2 * 64 * 4;
    cudaFuncSetAttribute(k_gemm1, cudaFuncAttributeMaxDynamicSharedMemorySize, smem_gemm1);
    cudaFuncSetAttribute(k_fused, cudaFuncAttributeMaxDynamicSharedMemorySize, smem_fused);

    void *px = nullptr, *pagg = nullptr;
    cudaGetSymbolAddress(&px, g_x);
    cudaGetSymbolAddress(&pagg, g_agg);

    cudaMemcpyAsync(px, x, sizeof(float) * N_NODES_C * NH, cudaMemcpyDeviceToDevice, 0);
    cudaMemsetAsync(pagg, 0, (size_t)N_NODES_C * NH * sizeof(float), 0);

    for (int l = 0; l < NLAYERS; l++) {
        k_prep<<<N_EDGES_C / 8, 256>>>(ei);
        k_gemm1<<<GRID_P, 256, smem_gemm1>>>(ei, ea, W1 + (size_t)l * DIN * NH);
        k_bnfin<<<1, 128>>>(gamma + l * NH, beta + l * NH);
        k_fused<<<GRID_P, 256, smem_fused>>>(ei,
                                             W2 + (size_t)l * NH * NH, b2 + l * NH,
                                             Wa + (size_t)l * NH * NH, ba + l * NH,
                                             Wb + l * NH,
                                             Wm + l * NH, bm + l);
        k_apply<<<(N_NODES_C * NH + 255) / 256, 256>>>();
    }
    k_head<<<(N_NODES_C + 7) / 8, 256>>>(We, be, out);
}

// round 3
// speedup vs baseline: 1.8394x; 1.8394x over previous
#include <cuda_runtime.h>
#include <mma.h>
#include <math.h>

using namespace nvcuda;

#define N_NODES_C 20000
#define N_EDGES_C 320000
#define NH 128
#define DIN 262
#define NLAYERS 3
#define BN_EPS 1e-5f
#define GRID_P 148

// ---------------- scratch ----------------
__device__ float g_x[N_NODES_C * NH];             // node features (10.24 MB)
__device__ float g_Y[(size_t)N_NODES_C * 256];    // [Y1 | Y2] per node (20.5 MB)
__device__ float g_norm[N_EDGES_C];
__device__ float g_dot[N_EDGES_C];
__device__ float g_stats[2 * NH];
__device__ float g_bnA[NH];
__device__ float g_bnB[NH];
__device__ float g_agg[N_NODES_C * NH];

__device__ __forceinline__ float psi_f(float z) {
    return copysignf(log1pf(fabsf(z)), z);
}
__device__ __forceinline__ float sigmoid_f(float z) {
    return 1.0f / (1.0f + expf(-z));
}
__device__ __forceinline__ float tf32r(float x) {
    return wmma::__float_to_tf32(x);
}

// ---------------- node GEMM: Y = X @ [W1a | W1b]  (20000 x 256 x 128) ----------------
// 256 threads, tile 64 nodes x 256 cols, warp grid 2x4, warp tile 32x64.
__global__ void __launch_bounds__(256, 1)
k_node(const float* __restrict__ W1) {
    extern __shared__ float sm[];
    float* Bs = sm;                 // 128 x 260
    float* As = sm + 128 * 260;     // 64 x 132

    int tid = threadIdx.x;
    int warp = tid >> 5;
    int wy = warp >> 2, wx = warp & 3;

    for (int idx = tid; idx < 128 * 256; idx += 256) {
        int k = idx >> 8, c = idx & 255;
        float v = (c < 128) ? W1[(size_t)k * NH + c] : W1[(size_t)(128 + k) * NH + (c - 128)];
        Bs[k * 260 + c] = tf32r(v);
    }

    const int NT = (N_NODES_C + 63) / 64;   // 313
    for (int tile = blockIdx.x; tile < NT; tile += GRID_P) {
        int n0 = tile * 64;
        __syncthreads();
        for (int idx = tid; idx < 64 * 32; idx += 256) {
            int e = idx >> 5, g = idx & 31;
            int r = n0 + e; if (r >= N_NODES_C) r = N_NODES_C - 1;
            float4 v = *(const float4*)&g_x[(size_t)r * NH + g * 4];
            float* dst = &As[e * 132 + g * 4];
            dst[0] = tf32r(v.x); dst[1] = tf32r(v.y);
            dst[2] = tf32r(v.z); dst[3] = tf32r(v.w);
        }
        __syncthreads();

        wmma::fragment<wmma::accumulator, 16, 16, 8, float> acc[2][4];
#pragma unroll
        for (int i = 0; i < 2; i++)
#pragma unroll
            for (int j = 0; j < 4; j++) wmma::fill_fragment(acc[i][j], 0.f);

#pragma unroll
        for (int kk = 0; kk < NH; kk += 8) {
            wmma::fragment<wmma::matrix_a, 16, 16, 8, wmma::precision::tf32, wmma::row_major> a0, a1;
            wmma::load_matrix_sync(a0, &As[(wy * 32) * 132 + kk], 132);
            wmma::load_matrix_sync(a1, &As[(wy * 32 + 16) * 132 + kk], 132);
#pragma unroll
            for (int j = 0; j < 4; j++) {
                wmma::fragment<wmma::matrix_b, 16, 16, 8, wmma::precision::tf32, wmma::row_major> bf;
                wmma::load_matrix_sync(bf, &Bs[kk * 260 + wx * 64 + j * 16], 260);
                wmma::mma_sync(acc[0][j], a0, bf, acc[0][j]);
                wmma::mma_sync(acc[1][j], a1, bf, acc[1][j]);
            }
        }
#pragma unroll
        for (int i = 0; i < 2; i++) {
            int row0 = n0 + wy * 32 + i * 16;
            if (row0 + 16 <= N_NODES_C) {
#pragma unroll
                for (int j = 0; j < 4; j++)
                    wmma::store_matrix_sync(&g_Y[(size_t)row0 * 256 + wx * 64 + j * 16],
                                            acc[i][j], 256, wmma::mem_row_major);
            }
        }
    }
}

// ---------------- stats pass: norms/dots + BN column sums (hpre never stored) --------
__global__ void __launch_bounds__(256)
k_stats(const int* __restrict__ ei, const float* __restrict__ ea,
        const float* __restrict__ W1c) {   // W1c = W1 + 256*NH (6 x 128)
    __shared__ float w1c[6 * 128];
    __shared__ float red[2 * 128];

    int tid = threadIdx.x;
    int warp = tid >> 5, lane = tid & 31;
    for (int i = tid; i < 6 * 128; i += 256) w1c[i] = W1c[i];
    if (tid < 256) red[tid] = 0.f;
    __syncthreads();

    float acc_s[4] = {0.f, 0.f, 0.f, 0.f};
    float acc_q[4] = {0.f, 0.f, 0.f, 0.f};
    int col = lane * 4;
    float sgn0 = (lane == 0) ? 1.f : -1.f;

    int gw = blockIdx.x * 8 + warp;
    int tw = gridDim.x * 8;
    for (int e = gw; e < N_EDGES_C; e += tw) {
        int r = ei[e];
        int c = ei[N_EDGES_C + e];
        float4 xr = *(const float4*)&g_x[(size_t)r * NH + col];
        float4 xc = *(const float4*)&g_x[(size_t)c * NH + col];
        float dx = xr.x - xc.x, dy = xr.y - xc.y, dz = xr.z - xc.z, dw = xr.w - xc.w;
        float dd = sgn0 * dx * dx - dy * dy - dz * dz - dw * dw;
        float ij = sgn0 * xr.x * xc.x - xr.y * xc.y - xr.z * xc.z - xr.w * xc.w;
#pragma unroll
        for (int o = 16; o; o >>= 1) {
            dd += __shfl_xor_sync(0xffffffffu, dd, o);
            ij += __shfl_xor_sync(0xffffffffu, ij, o);
        }
        float nrm = psi_f(dd), dt = psi_f(ij);
        if (lane == 0) { g_norm[e] = nrm; g_dot[e] = dt; }

        float4 y1 = *(const float4*)&g_Y[(size_t)r * 256 + col];
        float4 y2 = *(const float4*)&g_Y[(size_t)c * 256 + 128 + col];
        float4 eav = *(const float4*)&ea[(size_t)e * 4];
        float hv[4] = {y1.x + y2.x, y1.y + y2.y, y1.z + y2.z, y1.w + y2.w};
#pragma unroll
        for (int j = 0; j < 4; j++) {
            int cc = col + j;
            float h = hv[j];
            h = fmaf(eav.x, w1c[cc], h);
            h = fmaf(eav.y, w1c[128 + cc], h);
            h = fmaf(eav.z, w1c[256 + cc], h);
            h = fmaf(eav.w, w1c[384 + cc], h);
            h = fmaf(nrm, w1c[512 + cc], h);
            h = fmaf(dt, w1c[640 + cc], h);
            acc_s[j] += h;
            acc_q[j] = fmaf(h, h, acc_q[j]);
        }
    }
#pragma unroll
    for (int j = 0; j < 4; j++) {
        atomicAdd(&red[col + j], acc_s[j]);
        atomicAdd(&red[128 + col + j], acc_q[j]);
    }
    __syncthreads();
    if (tid < 256) atomicAdd(&g_stats[tid], red[tid]);
}

// ---------------- BN finalize (resets stats) -----------------------------------------
__global__ void k_bnfin(const float* __restrict__ gamma, const float* __restrict__ beta) {
    int c = threadIdx.x;
    float inv = 1.f / (float)N_EDGES_C;
    float mean = g_stats[c] * inv;
    float var = g_stats[NH + c] * inv - mean * mean;
    float sc = gamma[c] * rsqrtf(var + BN_EPS);
    g_bnA[c] = sc;
    g_bnB[c] = beta[c] - mean * sc;
    g_stats[c] = 0.f;
    g_stats[NH + c] = 0.f;
}

// ---------------- fused edge MLP (512 threads, 128-edge tiles, in-place S) -----------
__global__ void __launch_bounds__(512, 1)
k_fused(const int* __restrict__ ei, const float* __restrict__ ea,
        const float* __restrict__ W1c,
        const float* __restrict__ W2, const float* __restrict__ b2,
        const float* __restrict__ Wa, const float* __restrict__ ba,
        const float* __restrict__ Wb,
        const float* __restrict__ Wm, const float* __restrict__ bm) {
    extern __shared__ float sm[];
    float* W2s = sm;                        // 128*132
    float* Was = W2s + NH * 132;            // 128*132
    float* S   = Was + NH * 132;            // 128*132 (in-place reuse)
    float* p_bnA = S + 128 * 132;
    float* p_bnB = p_bnA + NH;
    float* p_b2  = p_bnB + NH;
    float* p_ba  = p_b2 + NH;
    float* p_Wm  = p_ba + NH;
    float* p_Wb  = p_Wm + NH;
    float* w1c   = p_Wb + NH;               // 6*128
    float* s_sh  = w1c + 6 * 128;           // 128
    int*   srow  = (int*)(s_sh + 128);      // 128
    int*   scol  = srow + 128;              // 128

    int tid = threadIdx.x;
    int warp = tid >> 5, lane = tid & 31;
    int wy = warp >> 2, wx = warp & 3;      // 4 x 4 warp grid
    float bmv = bm[0];

    for (int idx = tid; idx < NH * NH; idx += 512) {
        int k = idx >> 7, c = idx & 127;
        W2s[k * 132 + c] = tf32r(W2[idx]);
        Was[k * 132 + c] = tf32r(Wa[idx]);
    }
    for (int i = tid; i < 6 * 128; i += 512) w1c[i] = W1c[i];
    if (tid < NH) {
        p_bnA[tid] = g_bnA[tid];
        p_bnB[tid] = g_bnB[tid];
        p_b2[tid]  = b2[tid];
        p_ba[tid]  = ba[tid];
        p_Wm[tid]  = Wm[tid];
        p_Wb[tid]  = Wb[tid];
    }

    const int NT = N_EDGES_C / 128;         // 2500
    for (int tile = blockIdx.x; tile < NT; tile += GRID_P) {
        int e0 = tile * 128;
        __syncthreads();
        if (tid < 128) srow[tid] = ei[e0 + tid];
        else if (tid < 256) scol[tid - 128] = ei[N_EDGES_C + e0 + tid - 128];
        __syncthreads();

        // recompute hpre = Y1[r] + Y2[c] + E(e), BN + ReLU -> S (tf32)
        for (int idx = tid; idx < 128 * 32; idx += 512) {
            int e = idx >> 5, g = idx & 31;
            int kg = g * 4;
            int r = srow[e], c = scol[e];
            float4 y1 = *(const float4*)&g_Y[(size_t)r * 256 + kg];
            float4 y2 = *(const float4*)&g_Y[(size_t)c * 256 + 128 + kg];
            float4 eav = *(const float4*)&ea[(size_t)(e0 + e) * 4];
            float nrm = g_norm[e0 + e], dt = g_dot[e0 + e];
            float hv[4] = {y1.x + y2.x, y1.y + y2.y, y1.z + y2.z, y1.w + y2.w};
            float* dst = &S[e * 132 + kg];
#pragma unroll
            for (int j = 0; j < 4; j++) {
                int cc = kg + j;
                float h = hv[j];
                h = fmaf(eav.x, w1c[cc], h);
                h = fmaf(eav.y, w1c[128 + cc], h);
                h = fmaf(eav.z, w1c[256 + cc], h);
                h = fmaf(eav.w, w1c[384 + cc], h);
                h = fmaf(nrm, w1c[512 + cc], h);
                h = fmaf(dt, w1c[640 + cc], h);
                h = fmaxf(fmaf(h, p_bnA[cc], p_bnB[cc]), 0.f);
                dst[j] = tf32r(h);
            }
        }
        __syncthreads();

        // GEMM1: acc = S @ W2   (warp tile 32x32)
        wmma::fragment<wmma::accumulator, 16, 16, 8, float> acc[2][2];
#pragma unroll
        for (int i = 0; i < 2; i++)
#pragma unroll
            for (int j = 0; j < 2; j++) wmma::fill_fragment(acc[i][j], 0.f);
#pragma unroll
        for (int kk = 0; kk < NH; kk += 8) {
            wmma::fragment<wmma::matrix_a, 16, 16, 8, wmma::precision::tf32, wmma::row_major> a0, a1;
            wmma::fragment<wmma::matrix_b, 16, 16, 8, wmma::precision::tf32, wmma::row_major> b0, b1;
            wmma::load_matrix_sync(a0, &S[(wy * 32) * 132 + kk], 132);
            wmma::load_matrix_sync(a1, &S[(wy * 32 + 16) * 132 + kk], 132);
            wmma::load_matrix_sync(b0, &W2s[kk * 132 + wx * 32], 132);
            wmma::load_matrix_sync(b1, &W2s[kk * 132 + wx * 32 + 16], 132);
            wmma::mma_sync(acc[0][0], a0, b0, acc[0][0]);
            wmma::mma_sync(acc[0][1], a0, b1, acc[0][1]);
            wmma::mma_sync(acc[1][0], a1, b0, acc[1][0]);
            wmma::mma_sync(acc[1][1], a1, b1, acc[1][1]);
        }
        __syncthreads();   // all reads of S complete
#pragma unroll
        for (int i = 0; i < 2; i++)
#pragma unroll
            for (int j = 0; j < 2; j++)
                wmma::store_matrix_sync(&S[(wy * 32 + i * 16) * 132 + wx * 32 + j * 16],
                                        acc[i][j], 132, wmma::mem_row_major);
        __syncthreads();

        // bias + ReLU + sigmoid gate (each warp: 8 edges)
#pragma unroll
        for (int t = 0; t < 8; t++) {
            int e = warp * 8 + t;
            float v[4];
            float p = 0.f;
#pragma unroll
            for (int u = 0; u < 4; u++) {
                int c = lane + 32 * u;
                v[u] = fmaxf(S[e * 132 + c] + p_b2[c], 0.f);
                p = fmaf(v[u], p_Wm[c], p);
            }
#pragma unroll
            for (int o = 16; o; o >>= 1) p += __shfl_xor_sync(0xffffffffu, p, o);
            float wg = sigmoid_f(p + bmv);
#pragma unroll
            for (int u = 0; u < 4; u++) {
                int c = lane + 32 * u;
                S[e * 132 + c] = tf32r(v[u] * wg);
            }
        }
        __syncthreads();

        // GEMM2: acc = S @ Wa
#pragma unroll
        for (int i = 0; i < 2; i++)
#pragma unroll
            for (int j = 0; j < 2; j++) wmma::fill_fragment(acc[i][j], 0.f);
#pragma unroll
        for (int kk = 0; kk < NH; kk += 8) {
            wmma::fragment<wmma::matrix_a, 16, 16, 8, wmma::precision::tf32, wmma::row_major> a0, a1;
            wmma::fragment<wmma::matrix_b, 16, 16, 8, wmma::precision::tf32, wmma::row_major> b0, b1;
            wmma::load_matrix_sync(a0, &S[(wy * 32) * 132 + kk], 132);
            wmma::load_matrix_sync(a1, &S[(wy * 32 + 16) * 132 + kk], 132);
            wmma::load_matrix_sync(b0, &Was[kk * 132 + wx * 32], 132);
            wmma::load_matrix_sync(b1, &Was[kk * 132 + wx * 32 + 16], 132);
            wmma::mma_sync(acc[0][0], a0, b0, acc[0][0]);
            wmma::mma_sync(acc[0][1], a0, b1, acc[0][1]);
            wmma::mma_sync(acc[1][0], a1, b0, acc[1][0]);
            wmma::mma_sync(acc[1][1], a1, b1, acc[1][1]);
        }
        __syncthreads();
#pragma unroll
        for (int i = 0; i < 2; i++)
#pragma unroll
            for (int j = 0; j < 2; j++)
                wmma::store_matrix_sync(&S[(wy * 32 + i * 16) * 132 + wx * 32 + j * 16],
                                        acc[i][j], 132, wmma::mem_row_major);
        __syncthreads();

        // s = ReLU(S + ba) . Wb per edge
#pragma unroll
        for (int t = 0; t < 8; t++) {
            int e = warp * 8 + t;
            float p = 0.f;
#pragma unroll
            for (int u = 0; u < 4; u++) {
                int c = lane + 32 * u;
                p = fmaf(fmaxf(S[e * 132 + c] + p_ba[c], 0.f), p_Wb[c], p);
            }
#pragma unroll
            for (int o = 16; o; o >>= 1) p += __shfl_xor_sync(0xffffffffu, p, o);
            if (lane == 0) s_sh[e] = p;
        }
        __syncthreads();

        // scatter: clip(x_diff * s) into g_agg
        for (int idx = tid; idx < 128 * NH; idx += 512) {
            int el = idx >> 7, k = idx & 127;
            int r = srow[el], c = scol[el];
            float d = g_x[(size_t)r * NH + k] - g_x[(size_t)c * NH + k];
            float v = d * s_sh[el];
            v = fminf(fmaxf(v, -100.f), 100.f);
            atomicAdd(&g_agg[(size_t)r * NH + k], v);
        }
    }
}

// ---------------- x += agg; agg = 0 ---------------------------------------------------
__global__ void k_apply() {
    int i = blockIdx.x * 256 + threadIdx.x;
    if (i < N_NODES_C * NH) {
        g_x[i] += g_agg[i];
        g_agg[i] = 0.f;
    }
}

// ---------------- head ----------------------------------------------------------------
__global__ void k_head(const float* __restrict__ We, const float* __restrict__ be,
                       float* __restrict__ out) {
    int n = blockIdx.x * 8 + (threadIdx.x >> 5);
    if (n >= N_NODES_C) return;
    int lane = threadIdx.x & 31;
    const float* xr = g_x + (size_t)n * NH;
    float p0 = 0.f, p1 = 0.f;
#pragma unroll
    for (int u = 0; u < 4; u++) {
        int k = lane + 32 * u;
        float v = xr[k];
        p0 = fmaf(v, We[k * 2 + 0], p0);
        p1 = fmaf(v, We[k * 2 + 1], p1);
    }
#pragma unroll
    for (int o = 16; o; o >>= 1) {
        p0 += __shfl_xor_sync(0xffffffffu, p0, o);
        p1 += __shfl_xor_sync(0xffffffffu, p1, o);
    }
    if (lane == 0) {
        out[(size_t)n * 2 + 0] = sigmoid_f(p0 + be[0]);
        out[(size_t)n * 2 + 1] = sigmoid_f(p1 + be[1]);
    }
}

// ---------------- launch ---------------------------------------------------------------
extern "C" void kernel_launch(void* const* d_in, const int* in_sizes, int n_in,
                              void* d_out, int out_size) {
    (void)in_sizes; (void)n_in; (void)out_size;
    const float* x     = (const float*)d_in[0];
    const int*   ei    = (const int*)d_in[1];
    const float* ea    = (const float*)d_in[2];
    const float* W1    = (const float*)d_in[3];
    const float* gamma = (const float*)d_in[4];
    const float* beta  = (const float*)d_in[5];
    const float* W2    = (const float*)d_in[6];
    const float* b2    = (const float*)d_in[7];
    const float* Wa    = (const float*)d_in[8];
    const float* ba    = (const float*)d_in[9];
    const float* Wb    = (const float*)d_in[10];
    const float* Wm    = (const float*)d_in[11];
    const float* bm    = (const float*)d_in[12];
    const float* We    = (const float*)d_in[13];
    const float* be    = (const float*)d_in[14];
    float* out = (float*)d_out;

    const int smem_node  = (128 * 260 + 64 * 132) * 4;
    const int smem_fused = (3 * NH * 132 + 6 * NH + 6 * 128 + 128) * 4 + 2 * 128 * 4;
    cudaFuncSetAttribute(k_node,  cudaFuncAttributeMaxDynamicSharedMemorySize, smem_node);
    cudaFuncSetAttribute(k_fused, cudaFuncAttributeMaxDynamicSharedMemorySize, smem_fused);

    void *px = nullptr, *pagg = nullptr;
    cudaGetSymbolAddress(&px, g_x);
    cudaGetSymbolAddress(&pagg, g_agg);

    cudaMemcpyAsync(px, x, sizeof(float) * N_NODES_C * NH, cudaMemcpyDeviceToDevice, 0);
    cudaMemsetAsync(pagg, 0, (size_t)N_NODES_C * NH * sizeof(float), 0);

    for (int l = 0; l < NLAYERS; l++) {
        const float* W1l = W1 + (size_t)l * DIN * NH;
        k_node<<<GRID_P, 256, smem_node>>>(W1l);
        k_stats<<<1184, 256>>>(ei, ea, W1l + 256 * NH);
        k_bnfin<<<1, 128>>>(gamma + l * NH, beta + l * NH);
        k_fused<<<GRID_P, 512, smem_fused>>>(ei, ea, W1l + 256 * NH,
                                             W2 + (size_t)l * NH * NH, b2 + l * NH,
                                             Wa + (size_t)l * NH * NH, ba + l * NH,
                                             Wb + l * NH,
                                             Wm + l * NH, bm + l);
        k_apply<<<(N_NODES_C * NH + 255) / 256, 256>>>();
    }
    k_head<<<(N_NODES_C + 7) / 8, 256>>>(We, be, out);
}

// round 4
// speedup vs baseline: 2.9997x; 1.6308x over previous
#include <cuda_runtime.h>
#include <cuda_bf16.h>
#include <mma.h>
#include <math.h>

using namespace nvcuda;

#define N_NODES_C 20000
#define N_EDGES_C 320000
#define NH 128
#define DIN 262
#define NLAYERS 3
#define BN_EPS 1e-5f
#define GRID_P 148

// ---------------- scratch ----------------
__device__ float g_x[N_NODES_C * NH];             // node features buffer A
__device__ float g_x2[N_NODES_C * NH];            // node features buffer B (ping-pong)
__device__ float g_Y[(size_t)N_NODES_C * 256];    // [Y1 | Y2] per node (20.5 MB)
__device__ float g_norm[N_EDGES_C];
__device__ float g_dot[N_EDGES_C];
__device__ float g_s[N_EDGES_C];                  // per-edge phi_x scalar
__device__ float g_stats[2 * NH];
__device__ float g_bnA[NH];
__device__ float g_bnB[NH];
__device__ int   g_cnt[N_NODES_C];                // degree histogram / fill cursor
__device__ int   g_rowptr[N_NODES_C + 1];         // CSR row pointers
__device__ int   g_eidx[N_EDGES_C];               // CSR edge ids

__device__ __forceinline__ float psi_f(float z) {
    return copysignf(log1pf(fabsf(z)), z);
}
__device__ __forceinline__ float sigmoid_f(float z) {
    return 1.0f / (1.0f + expf(-z));
}
__device__ __forceinline__ __nv_bfloat16 bf(float x) { return __float2bfloat16(x); }

typedef wmma::fragment<wmma::matrix_a, 16, 16, 16, __nv_bfloat16, wmma::row_major> FragA;
typedef wmma::fragment<wmma::matrix_b, 16, 16, 16, __nv_bfloat16, wmma::row_major> FragB;
typedef wmma::fragment<wmma::accumulator, 16, 16, 16, float> FragC;

// ================= CSR build (once per launch; edge_index is a fixed input) ==========
__global__ void k_hist(const int* __restrict__ ei) {
    int e = blockIdx.x * 256 + threadIdx.x;
    if (e < N_EDGES_C) atomicAdd(&g_cnt[ei[e]], 1);
}

__global__ void k_scan() {   // single block, 1024 threads, 20 nodes each
    __shared__ int part[1024];
    int t = threadIdx.x;
    int base = t * 20;
    int s = 0;
    for (int i = 0; i < 20; i++) {
        int idx = base + i;
        if (idx < N_NODES_C) s += g_cnt[idx];
    }
    part[t] = s;
    __syncthreads();
    for (int off = 1; off < 1024; off <<= 1) {
        int v = (t >= off) ? part[t - off] : 0;
        __syncthreads();
        part[t] += v;
        __syncthreads();
    }
    int run = (t == 0) ? 0 : part[t - 1];
    for (int i = 0; i < 20; i++) {
        int idx = base + i;
        if (idx <= N_NODES_C) g_rowptr[idx] = run;
        if (idx < N_NODES_C) run += g_cnt[idx];
    }
    for (int i = 0; i < 20; i++) {   // reset for cursor use
        int idx = base + i;
        if (idx < N_NODES_C) g_cnt[idx] = 0;
    }
}

__global__ void k_fillcsr(const int* __restrict__ ei) {
    int e = blockIdx.x * 256 + threadIdx.x;
    if (e < N_EDGES_C) {
        int r = ei[e];
        int slot = g_rowptr[r] + atomicAdd(&g_cnt[r], 1);
        g_eidx[slot] = e;
    }
}

__global__ void k_sortseg() {   // deterministic within-node order (insertion sort)
    int n = blockIdx.x * 256 + threadIdx.x;
    if (n >= N_NODES_C) return;
    int beg = g_rowptr[n], end = g_rowptr[n + 1];
    for (int i = beg + 1; i < end; i++) {
        int v = g_eidx[i], j = i - 1;
        while (j >= beg && g_eidx[j] > v) { g_eidx[j + 1] = g_eidx[j]; j--; }
        g_eidx[j + 1] = v;
    }
}

// ================= node GEMM: Y = X @ [W1a | W1b]  (bf16, 20000 x 256 x 128) =========
// 256 threads (8 warps, 2x4), tile 64 nodes x 256 cols, warp tile 32x64.
__global__ void __launch_bounds__(256, 1)
k_node(const float* __restrict__ xin, const float* __restrict__ W1) {
    extern __shared__ __align__(16) char smraw[];
    __nv_bfloat16* Bs = (__nv_bfloat16*)smraw;        // 128 x 264
    __nv_bfloat16* As = Bs + 128 * 264;               // 64 x 136

    int tid = threadIdx.x;
    int warp = tid >> 5;
    int wy = warp >> 2, wx = warp & 3;

    for (int idx = tid; idx < 128 * 256; idx += 256) {
        int k = idx >> 8, c = idx & 255;
        float v = (c < 128) ? W1[(size_t)k * NH + c] : W1[(size_t)(128 + k) * NH + (c - 128)];
        Bs[k * 264 + c] = bf(v);
    }

    const int NT = (N_NODES_C + 63) / 64;   // 313
    for (int tile = blockIdx.x; tile < NT; tile += GRID_P) {
        int n0 = tile * 64;
        __syncthreads();
        for (int idx = tid; idx < 64 * 32; idx += 256) {
            int e = idx >> 5, g = idx & 31;
            int r = n0 + e; if (r >= N_NODES_C) r = N_NODES_C - 1;
            float4 v = *(const float4*)&xin[(size_t)r * NH + g * 4];
            __nv_bfloat16* dst = &As[e * 136 + g * 4];
            dst[0] = bf(v.x); dst[1] = bf(v.y); dst[2] = bf(v.z); dst[3] = bf(v.w);
        }
        __syncthreads();

        FragC acc[2][4];
#pragma unroll
        for (int i = 0; i < 2; i++)
#pragma unroll
            for (int j = 0; j < 4; j++) wmma::fill_fragment(acc[i][j], 0.f);

#pragma unroll
        for (int kk = 0; kk < NH; kk += 16) {
            FragA a0, a1;
            wmma::load_matrix_sync(a0, &As[(wy * 32) * 136 + kk], 136);
            wmma::load_matrix_sync(a1, &As[(wy * 32 + 16) * 136 + kk], 136);
#pragma unroll
            for (int j = 0; j < 4; j++) {
                FragB bfr;
                wmma::load_matrix_sync(bfr, &Bs[kk * 264 + wx * 64 + j * 16], 264);
                wmma::mma_sync(acc[0][j], a0, bfr, acc[0][j]);
                wmma::mma_sync(acc[1][j], a1, bfr, acc[1][j]);
            }
        }
#pragma unroll
        for (int i = 0; i < 2; i++) {
            int row0 = n0 + wy * 32 + i * 16;
            if (row0 + 16 <= N_NODES_C) {
#pragma unroll
                for (int j = 0; j < 4; j++)
                    wmma::store_matrix_sync(&g_Y[(size_t)row0 * 256 + wx * 64 + j * 16],
                                            acc[i][j], 256, wmma::mem_row_major);
            }
        }
    }
}

// ================= stats pass: norms/dots + BN column sums ===========================
__global__ void __launch_bounds__(256)
k_stats(const float* __restrict__ xin, const int* __restrict__ ei,
        const float* __restrict__ ea, const float* __restrict__ W1c) {
    __shared__ float w1c[6 * 128];
    __shared__ float red[2 * 128];

    int tid = threadIdx.x;
    int warp = tid >> 5, lane = tid & 31;
    for (int i = tid; i < 6 * 128; i += 256) w1c[i] = W1c[i];
    if (tid < 256) red[tid] = 0.f;
    __syncthreads();

    float acc_s[4] = {0.f, 0.f, 0.f, 0.f};
    float acc_q[4] = {0.f, 0.f, 0.f, 0.f};
    int col = lane * 4;
    float sgn0 = (lane == 0) ? 1.f : -1.f;

    int gw = blockIdx.x * 8 + warp;
    int tw = gridDim.x * 8;
    for (int e = gw; e < N_EDGES_C; e += tw) {
        int r = ei[e];
        int c = ei[N_EDGES_C + e];
        float4 xr = *(const float4*)&xin[(size_t)r * NH + col];
        float4 xc = *(const float4*)&xin[(size_t)c * NH + col];
        float dx = xr.x - xc.x, dy = xr.y - xc.y, dz = xr.z - xc.z, dw = xr.w - xc.w;
        float dd = sgn0 * dx * dx - dy * dy - dz * dz - dw * dw;
        float ij = sgn0 * xr.x * xc.x - xr.y * xc.y - xr.z * xc.z - xr.w * xc.w;
#pragma unroll
        for (int o = 16; o; o >>= 1) {
            dd += __shfl_xor_sync(0xffffffffu, dd, o);
            ij += __shfl_xor_sync(0xffffffffu, ij, o);
        }
        float nrm = psi_f(dd), dt = psi_f(ij);
        if (lane == 0) { g_norm[e] = nrm; g_dot[e] = dt; }

        float4 y1 = *(const float4*)&g_Y[(size_t)r * 256 + col];
        float4 y2 = *(const float4*)&g_Y[(size_t)c * 256 + 128 + col];
        float4 eav = *(const float4*)&ea[(size_t)e * 4];
        float hv[4] = {y1.x + y2.x, y1.y + y2.y, y1.z + y2.z, y1.w + y2.w};
#pragma unroll
        for (int j = 0; j < 4; j++) {
            int cc = col + j;
            float h = hv[j];
            h = fmaf(eav.x, w1c[cc], h);
            h = fmaf(eav.y, w1c[128 + cc], h);
            h = fmaf(eav.z, w1c[256 + cc], h);
            h = fmaf(eav.w, w1c[384 + cc], h);
            h = fmaf(nrm, w1c[512 + cc], h);
            h = fmaf(dt, w1c[640 + cc], h);
            acc_s[j] += h;
            acc_q[j] = fmaf(h, h, acc_q[j]);
        }
    }
#pragma unroll
    for (int j = 0; j < 4; j++) {
        atomicAdd(&red[col + j], acc_s[j]);
        atomicAdd(&red[128 + col + j], acc_q[j]);
    }
    __syncthreads();
    if (tid < 256) atomicAdd(&g_stats[tid], red[tid]);
}

// ================= BN finalize (resets stats) ========================================
__global__ void k_bnfin(const float* __restrict__ gamma, const float* __restrict__ beta) {
    int c = threadIdx.x;
    float inv = 1.f / (float)N_EDGES_C;
    float mean = g_stats[c] * inv;
    float var = g_stats[NH + c] * inv - mean * mean;
    float sc = gamma[c] * rsqrtf(var + BN_EPS);
    g_bnA[c] = sc;
    g_bnB[c] = beta[c] - mean * sc;
    g_stats[c] = 0.f;
    g_stats[NH + c] = 0.f;
}

// ================= fused edge MLP (bf16 MMA, writes per-edge scalar g_s) =============
// 512 threads (16 warps, 4x4), tile 128 edges, warp tile 32x32.
__global__ void __launch_bounds__(512, 1)
k_fused(const int* __restrict__ ei, const float* __restrict__ ea,
        const float* __restrict__ W1c,
        const float* __restrict__ W2, const float* __restrict__ b2,
        const float* __restrict__ Wa, const float* __restrict__ ba,
        const float* __restrict__ Wb,
        const float* __restrict__ Wm, const float* __restrict__ bm) {
    extern __shared__ __align__(16) char smraw[];
    __nv_bfloat16* W2s = (__nv_bfloat16*)smraw;       // 128 x 136
    __nv_bfloat16* Was = W2s + 128 * 136;             // 128 x 136
    __nv_bfloat16* S   = Was + 128 * 136;             // 128 x 136 (bf16 A operand)
    float* Sf   = (float*)(S + 128 * 136);            // 128 x 132 (fp32 GEMM staging)
    float* w1c  = Sf + 128 * 132;                     // 6*128
    float* p_bnA = w1c + 768;
    float* p_bnB = p_bnA + NH;
    float* p_b2  = p_bnB + NH;
    float* p_ba  = p_b2 + NH;
    float* p_Wm  = p_ba + NH;
    float* p_Wb  = p_Wm + NH;

    int tid = threadIdx.x;
    int warp = tid >> 5, lane = tid & 31;
    int wy = warp >> 2, wx = warp & 3;                // 4 x 4 warp grid
    float bmv = bm[0];

    for (int idx = tid; idx < NH * NH; idx += 512) {
        int k = idx >> 7, c = idx & 127;
        W2s[k * 136 + c] = bf(W2[idx]);
        Was[k * 136 + c] = bf(Wa[idx]);
    }
    for (int i = tid; i < 6 * 128; i += 512) w1c[i] = W1c[i];
    if (tid < NH) {
        p_bnA[tid] = g_bnA[tid];
        p_bnB[tid] = g_bnB[tid];
        p_b2[tid]  = b2[tid];
        p_ba[tid]  = ba[tid];
        p_Wm[tid]  = Wm[tid];
        p_Wb[tid]  = Wb[tid];
    }

    const int NT = N_EDGES_C / 128;         // 2500
    for (int tile = blockIdx.x; tile < NT; tile += GRID_P) {
        int e0 = tile * 128;
        __syncthreads();   // prior tile's phase5 reads done; weights ready (1st iter)

        // phase 1: hpre = Y1[r] + Y2[c] + E(e); BN + ReLU -> S (bf16)
        for (int idx = tid; idx < 128 * 32; idx += 512) {
            int e = idx >> 5, g = idx & 31;
            int kg = g * 4;
            int r = ei[e0 + e];
            int c = ei[N_EDGES_C + e0 + e];
            float4 y1 = *(const float4*)&g_Y[(size_t)r * 256 + kg];
            float4 y2 = *(const float4*)&g_Y[(size_t)c * 256 + 128 + kg];
            float4 eav = *(const float4*)&ea[(size_t)(e0 + e) * 4];
            float nrm = g_norm[e0 + e], dt = g_dot[e0 + e];
            float hv[4] = {y1.x + y2.x, y1.y + y2.y, y1.z + y2.z, y1.w + y2.w};
            __nv_bfloat16* dst = &S[e * 136 + kg];
#pragma unroll
            for (int j = 0; j < 4; j++) {
                int cc = kg + j;
                float h = hv[j];
                h = fmaf(eav.x, w1c[cc], h);
                h = fmaf(eav.y, w1c[128 + cc], h);
                h = fmaf(eav.z, w1c[256 + cc], h);
                h = fmaf(eav.w, w1c[384 + cc], h);
                h = fmaf(nrm, w1c[512 + cc], h);
                h = fmaf(dt, w1c[640 + cc], h);
                h = fmaxf(fmaf(h, p_bnA[cc], p_bnB[cc]), 0.f);
                dst[j] = bf(h);
            }
        }
        __syncthreads();

        // phase 2: Sf = S @ W2
        {
            FragC acc[2][2];
#pragma unroll
            for (int i = 0; i < 2; i++)
#pragma unroll
                for (int j = 0; j < 2; j++) wmma::fill_fragment(acc[i][j], 0.f);
#pragma unroll
            for (int kk = 0; kk < NH; kk += 16) {
                FragA a0, a1; FragB b0, b1;
                wmma::load_matrix_sync(a0, &S[(wy * 32) * 136 + kk], 136);
                wmma::load_matrix_sync(a1, &S[(wy * 32 + 16) * 136 + kk], 136);
                wmma::load_matrix_sync(b0, &W2s[kk * 136 + wx * 32], 136);
                wmma::load_matrix_sync(b1, &W2s[kk * 136 + wx * 32 + 16], 136);
                wmma::mma_sync(acc[0][0], a0, b0, acc[0][0]);
                wmma::mma_sync(acc[0][1], a0, b1, acc[0][1]);
                wmma::mma_sync(acc[1][0], a1, b0, acc[1][0]);
                wmma::mma_sync(acc[1][1], a1, b1, acc[1][1]);
            }
#pragma unroll
            for (int i = 0; i < 2; i++)
#pragma unroll
                for (int j = 0; j < 2; j++)
                    wmma::store_matrix_sync(&Sf[(wy * 32 + i * 16) * 132 + wx * 32 + j * 16],
                                            acc[i][j], 132, wmma::mem_row_major);
        }
        __syncthreads();

        // phase 3: bias + ReLU + sigmoid gate (warp: 8 edges) -> S (bf16)
#pragma unroll
        for (int t = 0; t < 8; t++) {
            int e = warp * 8 + t;
            float v[4];
            float p = 0.f;
#pragma unroll
            for (int u = 0; u < 4; u++) {
                int c = lane + 32 * u;
                v[u] = fmaxf(Sf[e * 132 + c] + p_b2[c], 0.f);
                p = fmaf(v[u], p_Wm[c], p);
            }
#pragma unroll
            for (int o = 16; o; o >>= 1) p += __shfl_xor_sync(0xffffffffu, p, o);
            float wg = sigmoid_f(p + bmv);
#pragma unroll
            for (int u = 0; u < 4; u++) {
                int c = lane + 32 * u;
                S[e * 136 + c] = bf(v[u] * wg);
            }
        }
        __syncthreads();

        // phase 4: Sf = S @ Wa
        {
            FragC acc[2][2];
#pragma unroll
            for (int i = 0; i < 2; i++)
#pragma unroll
                for (int j = 0; j < 2; j++) wmma::fill_fragment(acc[i][j], 0.f);
#pragma unroll
            for (int kk = 0; kk < NH; kk += 16) {
                FragA a0, a1; FragB b0, b1;
                wmma::load_matrix_sync(a0, &S[(wy * 32) * 136 + kk], 136);
                wmma::load_matrix_sync(a1, &S[(wy * 32 + 16) * 136 + kk], 136);
                wmma::load_matrix_sync(b0, &Was[kk * 136 + wx * 32], 136);
                wmma::load_matrix_sync(b1, &Was[kk * 136 + wx * 32 + 16], 136);
                wmma::mma_sync(acc[0][0], a0, b0, acc[0][0]);
                wmma::mma_sync(acc[0][1], a0, b1, acc[0][1]);
                wmma::mma_sync(acc[1][0], a1, b0, acc[1][0]);
                wmma::mma_sync(acc[1][1], a1, b1, acc[1][1]);
            }
#pragma unroll
            for (int i = 0; i < 2; i++)
#pragma unroll
                for (int j = 0; j < 2; j++)
                    wmma::store_matrix_sync(&Sf[(wy * 32 + i * 16) * 132 + wx * 32 + j * 16],
                                            acc[i][j], 132, wmma::mem_row_major);
        }
        __syncthreads();

        // phase 5: s = ReLU(Sf + ba) . Wb -> g_s  (warp: 8 edges)
#pragma unroll
        for (int t = 0; t < 8; t++) {
            int e = warp * 8 + t;
            float p = 0.f;
#pragma unroll
            for (int u = 0; u < 4; u++) {
                int c = lane + 32 * u;
                p = fmaf(fmaxf(Sf[e * 132 + c] + p_ba[c], 0.f), p_Wb[c], p);
            }
#pragma unroll
            for (int o = 16; o; o >>= 1) p += __shfl_xor_sync(0xffffffffu, p, o);
            if (lane == 0) g_s[e0 + e] = p;
        }
    }
}

// ================= aggregation: xout[n] = xin[n] + sum_e clip(x_diff * s) ============
__global__ void __launch_bounds__(256)
k_agg(const float* __restrict__ xin, float* __restrict__ xout,
      const int* __restrict__ ei) {
    int n = blockIdx.x * 8 + (threadIdx.x >> 5);
    if (n >= N_NODES_C) return;
    int lane = threadIdx.x & 31;
    float4 xi = *(const float4*)&xin[(size_t)n * NH + lane * 4];
    float4 acc = xi;
    int beg = g_rowptr[n], end = g_rowptr[n + 1];
    for (int j = beg; j < end; j++) {
        int e = g_eidx[j];
        float s = g_s[e];
        int c = ei[N_EDGES_C + e];
        float4 xc = *(const float4*)&xin[(size_t)c * NH + lane * 4];
        float tx = fminf(fmaxf((xi.x - xc.x) * s, -100.f), 100.f);
        float ty = fminf(fmaxf((xi.y - xc.y) * s, -100.f), 100.f);
        float tz = fminf(fmaxf((xi.z - xc.z) * s, -100.f), 100.f);
        float tw = fminf(fmaxf((xi.w - xc.w) * s, -100.f), 100.f);
        acc.x += tx; acc.y += ty; acc.z += tz; acc.w += tw;
    }
    *(float4*)&xout[(size_t)n * NH + lane * 4] = acc;
}

// ================= head ==============================================================
__global__ void k_head(const float* __restrict__ xfin,
                       const float* __restrict__ We, const float* __restrict__ be,
                       float* __restrict__ out) {
    int n = blockIdx.x * 8 + (threadIdx.x >> 5);
    if (n >= N_NODES_C) return;
    int lane = threadIdx.x & 31;
    const float* xr = xfin + (size_t)n * NH;
    float p0 = 0.f, p1 = 0.f;
#pragma unroll
    for (int u = 0; u < 4; u++) {
        int k = lane + 32 * u;
        float v = xr[k];
        p0 = fmaf(v, We[k * 2 + 0], p0);
        p1 = fmaf(v, We[k * 2 + 1], p1);
    }
#pragma unroll
    for (int o = 16; o; o >>= 1) {
        p0 += __shfl_xor_sync(0xffffffffu, p0, o);
        p1 += __shfl_xor_sync(0xffffffffu, p1, o);
    }
    if (lane == 0) {
        out[(size_t)n * 2 + 0] = sigmoid_f(p0 + be[0]);
        out[(size_t)n * 2 + 1] = sigmoid_f(p1 + be[1]);
    }
}

// ================= launch ============================================================
extern "C" void kernel_launch(void* const* d_in, const int* in_sizes, int n_in,
                              void* d_out, int out_size) {
    (void)in_sizes; (void)n_in; (void)out_size;
    const float* x     = (const float*)d_in[0];
    const int*   ei    = (const int*)d_in[1];
    const float* ea    = (const float*)d_in[2];
    const float* W1    = (const float*)d_in[3];
    const float* gamma = (const float*)d_in[4];
    const float* beta  = (const float*)d_in[5];
    const float* W2    = (const float*)d_in[6];
    const float* b2    = (const float*)d_in[7];
    const float* Wa    = (const float*)d_in[8];
    const float* ba    = (const float*)d_in[9];
    const float* Wb    = (const float*)d_in[10];
    const float* Wm    = (const float*)d_in[11];
    const float* bm    = (const float*)d_in[12];
    const float* We    = (const float*)d_in[13];
    const float* be    = (const float*)d_in[14];
    float* out = (float*)d_out;

    const int smem_node  = 128 * 264 * 2 + 64 * 136 * 2;                       // ~85 KB
    const int smem_fused = 3 * 128 * 136 * 2 + 128 * 132 * 4 + (768 + 6 * 128) * 4; // ~174 KB
    cudaFuncSetAttribute(k_node,  cudaFuncAttributeMaxDynamicSharedMemorySize, smem_node);
    cudaFuncSetAttribute(k_fused, cudaFuncAttributeMaxDynamicSharedMemorySize, smem_fused);

    void *px = nullptr, *pcnt = nullptr, *pstats = nullptr;
    cudaGetSymbolAddress(&px, g_x);
    cudaGetSymbolAddress(&pcnt, g_cnt);
    cudaGetSymbolAddress(&pstats, g_stats);

    cudaMemcpyAsync(px, x, sizeof(float) * N_NODES_C * NH, cudaMemcpyDeviceToDevice, 0);
    cudaMemsetAsync(pcnt, 0, N_NODES_C * sizeof(int), 0);
    cudaMemsetAsync(pstats, 0, 2 * NH * sizeof(float), 0);

    // CSR build (deterministic via per-node sort)
    k_hist<<<(N_EDGES_C + 255) / 256, 256>>>(ei);
    k_scan<<<1, 1024>>>();
    k_fillcsr<<<(N_EDGES_C + 255) / 256, 256>>>(ei);
    k_sortseg<<<(N_NODES_C + 255) / 256, 256>>>();

    void *px2 = nullptr;
    cudaGetSymbolAddress(&px2, g_x2);
    float* bufA = (float*)px;
    float* bufB = (float*)px2;

    for (int l = 0; l < NLAYERS; l++) {
        const float* W1l = W1 + (size_t)l * DIN * NH;
        const float* xin  = (l & 1) ? bufB : bufA;
        float*       xout = (l & 1) ? bufA : bufB;
        k_node<<<GRID_P, 256, smem_node>>>(xin, W1l);
        k_stats<<<1184, 256>>>(xin, ei, ea, W1l + 256 * NH);
        k_bnfin<<<1, 128>>>(gamma + l * NH, beta + l * NH);
        k_fused<<<GRID_P, 512, smem_fused>>>(ei, ea, W1l + 256 * NH,
                                             W2 + (size_t)l * NH * NH, b2 + l * NH,
                                             Wa + (size_t)l * NH * NH, ba + l * NH,
                                             Wb + l * NH,
                                             Wm + l * NH, bm + l);
        k_agg<<<(N_NODES_C + 7) / 8, 256>>>(xin, xout, ei);
    }
    // after 3 layers output is in bufB (A->B, B->A, A->B)
    k_head<<<(N_NODES_C + 7) / 8, 256>>>(bufB, We, be, out);
}